// round 1
// baseline (speedup 1.0000x reference)
#include <cuda_runtime.h>
#include <math.h>

#define BN 2
#define HH 256
#define WWD 256
#define CC 64
#define PIXB (HH*WWD)          // 65536 pixels per batch
#define NPIX (BN*PIXB)         // 131072
#define NCHUNK 512             // gram chunks of 256 pixels (256 per batch)

// ---------------- device scratch (no allocations allowed) ----------------
__device__ float g_v [NPIX*CC];
__device__ float g_m1[NPIX*CC];
__device__ float g_m2[NPIX*CC];
__device__ float g_t1[NPIX*CC];
__device__ float g_vm[NPIX*CC];
__device__ float g_gpart[NCHUNK*4096];
__device__ float g_gram [BN*4096];
__device__ float g_wfold[BN*4096];

__device__ __forceinline__ float dot4(float4 a, float4 b) {
    return a.x*b.x + a.y*b.y + a.z*b.z + a.w*b.w;
}
__device__ __forceinline__ float sigmf(float x) {
    return 1.0f / (1.0f + __expf(-x));
}
__device__ __forceinline__ float geluf(float v) {
    return 0.5f * v * (1.0f + erff(v * 0.70710678118654752f));
}

// ---------------- Gram partials: G_b = sum_n x x^T ----------------
// 512 chunks x 256 pixels. Thread (ti,tj) owns a 4x4 tile of the 64x64 Gram.
__global__ __launch_bounds__(256) void k_gram_part(const float* __restrict__ x)
{
    __shared__ float sx[8][64];
    int chunk = blockIdx.x;
    int base  = chunk * 256;          // pixel index (chunks never straddle batches)
    int tid = threadIdx.x;
    int ti = tid >> 4, tj = tid & 15;
    float a00=0,a01=0,a02=0,a03=0, a10=0,a11=0,a12=0,a13=0;
    float a20=0,a21=0,a22=0,a23=0, a30=0,a31=0,a32=0,a33=0;

    for (int pp = 0; pp < 256; pp += 8) {
        __syncthreads();
        int idx = tid * 2;
        int pr = idx >> 6, cc = idx & 63;
        float2 v2 = *(const float2*)&x[(size_t)(base + pp + pr)*CC + cc];
        sx[pr][cc] = v2.x; sx[pr][cc+1] = v2.y;
        __syncthreads();
        #pragma unroll
        for (int p = 0; p < 8; p++) {
            float4 xi = *(const float4*)&sx[p][4*ti];
            float4 xj = *(const float4*)&sx[p][4*tj];
            a00 += xi.x*xj.x; a01 += xi.x*xj.y; a02 += xi.x*xj.z; a03 += xi.x*xj.w;
            a10 += xi.y*xj.x; a11 += xi.y*xj.y; a12 += xi.y*xj.z; a13 += xi.y*xj.w;
            a20 += xi.z*xj.x; a21 += xi.z*xj.y; a22 += xi.z*xj.z; a23 += xi.z*xj.w;
            a30 += xi.w*xj.x; a31 += xi.w*xj.y; a32 += xi.w*xj.z; a33 += xi.w*xj.w;
        }
    }
    float* dst = &g_gpart[(size_t)chunk*4096];
    int r = 4*ti, c = 4*tj;
    dst[(r+0)*64+c+0]=a00; dst[(r+0)*64+c+1]=a01; dst[(r+0)*64+c+2]=a02; dst[(r+0)*64+c+3]=a03;
    dst[(r+1)*64+c+0]=a10; dst[(r+1)*64+c+1]=a11; dst[(r+1)*64+c+2]=a12; dst[(r+1)*64+c+3]=a13;
    dst[(r+2)*64+c+0]=a20; dst[(r+2)*64+c+1]=a21; dst[(r+2)*64+c+2]=a22; dst[(r+2)*64+c+3]=a23;
    dst[(r+3)*64+c+0]=a30; dst[(r+3)*64+c+1]=a31; dst[(r+3)*64+c+2]=a32; dst[(r+3)*64+c+3]=a33;
}

// deterministic fixed-order reduction of chunk partials
__global__ void k_gram_reduce()
{
    int e = blockIdx.x*blockDim.x + threadIdx.x;   // 0..8191
    if (e >= BN*4096) return;
    int b = e >> 12, i = e & 4095;
    float s = 0.f;
    for (int c = 0; c < NCHUNK/BN; c++)
        s += g_gpart[(size_t)(b*(NCHUNK/BN)+c)*4096 + i];
    g_gram[e] = s;
}

// ---------------- generic per-pixel 64x64 matvec (2 pixels/thread) ----------------
__global__ __launch_bounds__(128) void k_matvec(const float* __restrict__ in,
                                                const float* __restrict__ W,
                                                const float* __restrict__ bias,
                                                float* __restrict__ out)
{
    __shared__ float4 sW[CC*16];
    __shared__ float  sB[CC];
    for (int t = threadIdx.x; t < CC*16; t += blockDim.x) sW[t] = ((const float4*)W)[t];
    for (int t = threadIdx.x; t < CC; t += blockDim.x) sB[t] = bias ? bias[t] : 0.f;
    __syncthreads();

    int p0 = (blockIdx.x * blockDim.x + threadIdx.x) * 2;
    if (p0 >= NPIX) return;
    const float4* in4 = (const float4*)in;
    float4 x0[16], x1[16];
    #pragma unroll
    for (int i = 0; i < 16; i++) x0[i] = in4[(size_t)p0*16 + i];
    #pragma unroll
    for (int i = 0; i < 16; i++) x1[i] = in4[(size_t)(p0+1)*16 + i];

    float4* out4 = (float4*)out;
    for (int g = 0; g < 16; g++) {
        float4 a0, a1;
        a0.x = sB[4*g]; a0.y = sB[4*g+1]; a0.z = sB[4*g+2]; a0.w = sB[4*g+3];
        a1 = a0;
        #pragma unroll
        for (int i = 0; i < 16; i++) {
            float4 w0 = sW[(g*4+0)*16+i];
            float4 w1 = sW[(g*4+1)*16+i];
            float4 w2 = sW[(g*4+2)*16+i];
            float4 w3 = sW[(g*4+3)*16+i];
            a0.x += dot4(w0,x0[i]); a0.y += dot4(w1,x0[i]); a0.z += dot4(w2,x0[i]); a0.w += dot4(w3,x0[i]);
            a1.x += dot4(w0,x1[i]); a1.y += dot4(w1,x1[i]); a1.z += dot4(w2,x1[i]); a1.w += dot4(w3,x1[i]);
        }
        out4[(size_t)p0*16 + g] = a0;
        out4[(size_t)(p0+1)*16 + g] = a1;
    }
}

// ---------------- tiny solve: attn from Gram, fold Wp*A -> g_wfold ----------------
__global__ void k_small(const float* __restrict__ Wq, const float* __restrict__ Wk,
                        const float* __restrict__ Wp, const float* __restrict__ rs)
{
    __shared__ float sG[4096];
    __shared__ float sGq[4096];   // sGq[c*64+o] = (G Wq^T)[c][o]
    __shared__ float sLog[1024];  // [h*256 + d*16 + e]
    __shared__ float sNq[64], sNk[64];
    int tid = threadIdx.x;

    for (int b = 0; b < BN; b++) {
        for (int t = tid; t < 4096; t += 256) sG[t] = g_gram[b*4096 + t];
        __syncthreads();
        for (int t = tid; t < 4096; t += 256) {
            int c = t >> 6, o = t & 63;
            float s = 0.f;
            for (int i = 0; i < 64; i++) s += sG[c*64+i] * Wq[o*64+i];
            sGq[t] = s;
        }
        __syncthreads();
        if (tid < 64) {
            int o = tid;
            float qq = 0.f;
            for (int c = 0; c < 64; c++) qq += Wq[o*64+c] * sGq[c*64+o];
            sNq[o] = fmaxf(sqrtf(fmaxf(qq, 0.f)), 1e-12f);
            float kk = 0.f;
            for (int c = 0; c < 64; c++) {
                float gk = 0.f;
                for (int i = 0; i < 64; i++) gk += sG[c*64+i] * Wk[o*64+i];
                kk += Wk[o*64+c] * gk;
            }
            sNk[o] = fmaxf(sqrtf(fmaxf(kk, 0.f)), 1e-12f);
        }
        __syncthreads();
        for (int t = tid; t < 1024; t += 256) {
            int h = t >> 8, d = (t >> 4) & 15, e = t & 15;
            int rk = h*16 + d, rq = h*16 + e;
            float s = 0.f;
            for (int c = 0; c < 64; c++) s += Wk[rk*64+c] * sGq[c*64+rq];
            sLog[t] = s / (sNk[rk] * sNq[rq]) * rs[h];
        }
        __syncthreads();
        if (tid < 64) {                        // softmax over e per (h,d)
            float* row = &sLog[tid*16];
            float m = row[0];
            for (int e = 1; e < 16; e++) m = fmaxf(m, row[e]);
            float sum = 0.f;
            for (int e = 0; e < 16; e++) { float ev = expf(row[e]-m); row[e] = ev; sum += ev; }
            float inv = 1.f / sum;
            for (int e = 0; e < 16; e++) row[e] *= inv;
        }
        __syncthreads();
        for (int t = tid; t < 4096; t += 256) {  // Wfold = Wp * A (block-diag A)
            int o = t >> 6, j = t & 63, hj = j >> 4, ej = j & 15;
            float s = 0.f;
            for (int d = 0; d < 16; d++)
                s += Wp[o*64 + hj*16 + d] * sLog[(hj*16 + d)*16 + ej];
            g_wfold[b*4096 + t] = s;
        }
        __syncthreads();
    }
}

// ---------------- pe stage 1: t1 = gelu(dw3x3(x, pe_w1)) ----------------
__global__ __launch_bounds__(256) void k_pe1(const float* __restrict__ x,
                                             const float* __restrict__ w)
{
    __shared__ float sw[9*CC];   // [tap][c]
    for (int t = threadIdx.x; t < 9*CC; t += 256) { int c = t/9, k = t%9; sw[k*CC+c] = w[c*9+k]; }
    __syncthreads();
    int p = blockIdx.x*256 + threadIdx.x;
    int b = p >> 16, s = p & 65535, y = s >> 8, xx = s & 255;
    float4 acc[16];
    #pragma unroll
    for (int g = 0; g < 16; g++) { acc[g].x=0; acc[g].y=0; acc[g].z=0; acc[g].w=0; }
    const float4* x4 = (const float4*)x;
    const float4* sw4 = (const float4*)sw;
    #pragma unroll
    for (int ky = 0; ky < 3; ky++) {
        int yy = y + ky - 1; if (yy < 0 || yy >= HH) continue;
        #pragma unroll
        for (int kx = 0; kx < 3; kx++) {
            int xc = xx + kx - 1; if (xc < 0 || xc >= WWD) continue;
            size_t np = (size_t)((b<<16) + (yy<<8) + xc);
            int tap = ky*3 + kx;
            #pragma unroll
            for (int g = 0; g < 16; g++) {
                float4 v = x4[np*16+g], wv = sw4[tap*16+g];
                acc[g].x += wv.x*v.x; acc[g].y += wv.y*v.y; acc[g].z += wv.z*v.z; acc[g].w += wv.w*v.w;
            }
        }
    }
    float4* t14 = (float4*)g_t1;
    #pragma unroll
    for (int g = 0; g < 16; g++) {
        float4 r;
        r.x = geluf(acc[g].x); r.y = geluf(acc[g].y); r.z = geluf(acc[g].z); r.w = geluf(acc[g].w);
        t14[(size_t)p*16 + g] = r;
    }
}

// ---------------- mask mechanism: vm = v * m1 * (1 + sigmoid(dw5x5(m2))) --------
__global__ __launch_bounds__(256) void k_ma(const float* __restrict__ dw,
                                            const float* __restrict__ dwb)
{
    __shared__ float sdw[25*CC];
    __shared__ float sdb[CC];
    for (int t = threadIdx.x; t < 25*CC; t += 256) { int c = t/25, k = t%25; sdw[k*CC+c] = dw[c*25+k]; }
    for (int t = threadIdx.x; t < CC; t += 256) sdb[t] = dwb[t];
    __syncthreads();
    int p = blockIdx.x*256 + threadIdx.x;
    int b = p >> 16, s = p & 65535, y = s >> 8, xx = s & 255;
    float4 acc[16];
    #pragma unroll
    for (int g = 0; g < 16; g++) { acc[g].x=sdb[4*g]; acc[g].y=sdb[4*g+1]; acc[g].z=sdb[4*g+2]; acc[g].w=sdb[4*g+3]; }
    const float4* m24 = (const float4*)g_m2;
    const float4* sdw4 = (const float4*)sdw;
    for (int ky = 0; ky < 5; ky++) {
        int yy = y + ky - 2; if (yy < 0 || yy >= HH) continue;
        for (int kx = 0; kx < 5; kx++) {
            int xc = xx + kx - 2; if (xc < 0 || xc >= WWD) continue;
            size_t np = (size_t)((b<<16) + (yy<<8) + xc);
            int tap = ky*5 + kx;
            #pragma unroll
            for (int g = 0; g < 16; g++) {
                float4 mv = m24[np*16+g], wv = sdw4[tap*16+g];
                acc[g].x += wv.x*mv.x; acc[g].y += wv.y*mv.y; acc[g].z += wv.z*mv.z; acc[g].w += wv.w*mv.w;
            }
        }
    }
    const float4* m14 = (const float4*)g_m1;
    const float4* v4  = (const float4*)g_v;
    float4* vm4 = (float4*)g_vm;
    #pragma unroll
    for (int g = 0; g < 16; g++) {
        float4 m1v = m14[(size_t)p*16+g], vv = v4[(size_t)p*16+g];
        float4 r;
        r.x = vv.x * (m1v.x * (1.f + sigmf(acc[g].x)));
        r.y = vv.y * (m1v.y * (1.f + sigmf(acc[g].y)));
        r.z = vv.z * (m1v.z * (1.f + sigmf(acc[g].z)));
        r.w = vv.w * (m1v.w * (1.f + sigmf(acc[g].w)));
        vm4[(size_t)p*16 + g] = r;
    }
}

// ---------------- final: y = Wfold_b * vm + bp + dw3x3(t1, pe_w2) ----------------
__global__ __launch_bounds__(256) void k_out(const float* __restrict__ bp,
                                             const float* __restrict__ pe_w2,
                                             float* __restrict__ out)
{
    __shared__ float4 sW[CC*16];
    __shared__ float  sb[CC];
    __shared__ float  sw2[9*CC];
    int b = blockIdx.y;
    for (int t = threadIdx.x; t < CC*16; t += 256) sW[t] = ((const float4*)(g_wfold + b*4096))[t];
    for (int t = threadIdx.x; t < CC; t += 256) sb[t] = bp[t];
    for (int t = threadIdx.x; t < 9*CC; t += 256) { int c = t/9, k = t%9; sw2[k*CC+c] = pe_w2[c*9+k]; }
    __syncthreads();

    int s = blockIdx.x*256 + threadIdx.x;
    int p = b*PIXB + s;
    int y = s >> 8, xx = s & 255;
    float4 xv[16];
    const float4* vm4 = (const float4*)g_vm;
    #pragma unroll
    for (int i = 0; i < 16; i++) xv[i] = vm4[(size_t)p*16 + i];
    const float4* t14 = (const float4*)g_t1;
    const float4* sw24 = (const float4*)sw2;
    float4* out4 = (float4*)out;

    for (int g = 0; g < 16; g++) {
        float4 a;
        a.x = sb[4*g]; a.y = sb[4*g+1]; a.z = sb[4*g+2]; a.w = sb[4*g+3];
        #pragma unroll
        for (int i = 0; i < 16; i++) {
            float4 w0 = sW[(g*4+0)*16+i];
            float4 w1 = sW[(g*4+1)*16+i];
            float4 w2 = sW[(g*4+2)*16+i];
            float4 w3 = sW[(g*4+3)*16+i];
            a.x += dot4(w0,xv[i]); a.y += dot4(w1,xv[i]); a.z += dot4(w2,xv[i]); a.w += dot4(w3,xv[i]);
        }
        #pragma unroll
        for (int ky = 0; ky < 3; ky++) {
            int yy = y + ky - 1; if (yy < 0 || yy >= HH) continue;
            #pragma unroll
            for (int kx = 0; kx < 3; kx++) {
                int xc = xx + kx - 1; if (xc < 0 || xc >= WWD) continue;
                size_t np = (size_t)(b*PIXB + (yy<<8) + xc);
                float4 tv = t14[np*16+g];
                float4 wv = sw24[(ky*3+kx)*16+g];
                a.x += wv.x*tv.x; a.y += wv.y*tv.y; a.z += wv.z*tv.z; a.w += wv.w*tv.w;
            }
        }
        out4[(size_t)p*16 + g] = a;
    }
}

// ---------------- launcher ----------------
extern "C" void kernel_launch(void* const* d_in, const int* in_sizes, int n_in,
                              void* d_out, int out_size)
{
    const float* x_in   = (const float*)d_in[0];
    const float* mask   = (const float*)d_in[1];
    const float* Wq     = (const float*)d_in[2];
    const float* Wk     = (const float*)d_in[3];
    const float* Wv     = (const float*)d_in[4];
    const float* rescale= (const float*)d_in[5];
    const float* Wp     = (const float*)d_in[6];
    const float* bp     = (const float*)d_in[7];
    const float* mm_w1  = (const float*)d_in[8];
    const float* mm_b1  = (const float*)d_in[9];
    const float* mm_w2  = (const float*)d_in[10];
    const float* mm_b2  = (const float*)d_in[11];
    const float* mm_dw  = (const float*)d_in[12];
    const float* mm_dwb = (const float*)d_in[13];
    const float* pe_w1  = (const float*)d_in[14];
    const float* pe_w2  = (const float*)d_in[15];
    float* out = (float*)d_out;

    float *pm1, *pm2, *pv;
    cudaGetSymbolAddress((void**)&pm1, g_m1);
    cudaGetSymbolAddress((void**)&pm2, g_m2);
    cudaGetSymbolAddress((void**)&pv,  g_v);

    // q/k path collapses to the Gram matrix of x
    k_gram_part<<<NCHUNK, 256>>>(x_in);
    k_gram_reduce<<<(BN*4096 + 255)/256, 256>>>();
    k_small<<<1, 256>>>(Wq, Wk, Wp, rescale);

    // per-pixel matvecs
    k_matvec<<<NPIX/(128*2), 128>>>(mask, mm_w1, mm_b1, pm1);
    k_matvec<<<NPIX/(128*2), 128>>>(pm1,  mm_w2, mm_b2, pm2);
    k_matvec<<<NPIX/(128*2), 128>>>(x_in, Wv, nullptr, pv);

    // positional-embedding stage 1
    k_pe1<<<NPIX/256, 256>>>(x_in, pe_w1);

    // mask gate + v
    k_ma<<<NPIX/256, 256>>>(mm_dw, mm_dwb);

    // fused projection + pe stage 2
    k_out<<<dim3(PIXB/256, BN), 256>>>(bp, pe_w2, out);
}